// round 10
// baseline (speedup 1.0000x reference)
#include <cuda_runtime.h>
#include <cuda_bf16.h>
#include <cstdint>

// Problem constants
#define S_LEN  2048
#define BATCH  2
#define EMBED  1024
#define NHEAD  16
#define RANK   32
#define HDIM   64
#define MROWS  (BATCH * S_LEN)   // 4096
#define QKCOLS (NHEAD * RANK)    // 512
#define BH     (BATCH * NHEAD)   // 32

// ---------------------------------------------------------------------------
// Scratch (__device__ globals)
// ---------------------------------------------------------------------------
__device__ float g_QK[MROWS * 2 * QKCOLS];   // fused Q|K fp32 [4096][1024]
__device__ float g_V [MROWS * EMBED];
__device__ float g_AO[MROWS * EMBED];
__device__ float g_bqk[2 * QKCOLS];          // concat bias [1024]

__device__ __nv_bfloat16 g_Xhi [MROWS * EMBED];
__device__ __nv_bfloat16 g_Xlo [MROWS * EMBED];
__device__ __nv_bfloat16 g_AOhi[MROWS * EMBED];
__device__ __nv_bfloat16 g_AOlo[MROWS * EMBED];

__device__ __nv_bfloat16 g_Wqk_hi[2 * QKCOLS * EMBED];  // rows 0..511 Wq, 512..1023 Wk
__device__ __nv_bfloat16 g_Wqk_lo[2 * QKCOLS * EMBED];
__device__ __nv_bfloat16 g_Wv_hi[EMBED * EMBED];
__device__ __nv_bfloat16 g_Wv_lo[EMBED * EMBED];
__device__ __nv_bfloat16 g_Wo_hi[EMBED * EMBED];
__device__ __nv_bfloat16 g_Wo_lo[EMBED * EMBED];

// Attention-layout tensors
__device__ __nv_bfloat16 g_Qhi [MROWS * QKCOLS];   // [bh][S][32]
__device__ __nv_bfloat16 g_Qlo [MROWS * QKCOLS];
__device__ __nv_bfloat16 g_Khi [MROWS * QKCOLS];
__device__ __nv_bfloat16 g_Klo [MROWS * QKCOLS];
__device__ __nv_bfloat16 g_Vthi[BH * HDIM * S_LEN]; // [bh][d][S]
__device__ __nv_bfloat16 g_Vtlo[BH * HDIM * S_LEN];

// ---------------------------------------------------------------------------
// Helpers (compute_103-safe: mma.sync / ldmatrix / cp.async only)
// ---------------------------------------------------------------------------
__device__ __forceinline__ uint32_t smem_u32(const void* p) {
    uint32_t a;
    asm("{ .reg .u64 t; cvta.to.shared.u64 t, %1; cvt.u32.u64 %0, t; }"
        : "=r"(a) : "l"(p));
    return a;
}

__device__ __forceinline__ void cp16(uint32_t dst, const void* src) {
    asm volatile("cp.async.cg.shared.global [%0], [%1], 16;"
                 :: "r"(dst), "l"(src) : "memory");
}
__device__ __forceinline__ void cp_commit() {
    asm volatile("cp.async.commit_group;" ::: "memory");
}
template<int N> __device__ __forceinline__ void cp_wait() {
    asm volatile("cp.async.wait_group %0;" :: "n"(N) : "memory");
}

__device__ __forceinline__ void ldm_x4(uint32_t& r0, uint32_t& r1,
                                       uint32_t& r2, uint32_t& r3, uint32_t a) {
    asm volatile("ldmatrix.sync.aligned.m8n8.x4.shared.b16 {%0,%1,%2,%3}, [%4];"
                 : "=r"(r0), "=r"(r1), "=r"(r2), "=r"(r3) : "r"(a));
}

__device__ __forceinline__ void mma_bf16(float c[4], const uint32_t a[4],
                                         uint32_t b0, uint32_t b1) {
    asm volatile(
        "mma.sync.aligned.m16n8k16.row.col.f32.bf16.bf16.f32 "
        "{%0,%1,%2,%3}, {%4,%5,%6,%7}, {%8,%9}, {%0,%1,%2,%3};"
        : "+f"(c[0]), "+f"(c[1]), "+f"(c[2]), "+f"(c[3])
        : "r"(a[0]), "r"(a[1]), "r"(a[2]), "r"(a[3]), "r"(b0), "r"(b1));
}

__device__ __forceinline__ uint32_t pack_bf2(float lo, float hi) {
    __nv_bfloat162 t = __float22bfloat162_rn(make_float2(lo, hi));
    return *(uint32_t*)&t;
}

__device__ __forceinline__ void split1(float x, __nv_bfloat16& h, __nv_bfloat16& l) {
    h = __float2bfloat16(x);
    l = __float2bfloat16(x - __bfloat162float(h));
}

// pack (a,b) into bf16x2 hi + bf16x2 residual-lo; a -> lower halfword
__device__ __forceinline__ void split_pack2(float a, float b,
                                            uint32_t& h, uint32_t& l) {
    __nv_bfloat16 ah = __float2bfloat16(a);
    __nv_bfloat16 bh = __float2bfloat16(b);
    float ar = a - __bfloat162float(ah);
    float br = b - __bfloat162float(bh);
    __nv_bfloat162 th(ah, bh);
    h = *(uint32_t*)&th;
    l = pack_bf2(ar, br);
}

// ---------------------------------------------------------------------------
// Conversion kernels
// ---------------------------------------------------------------------------
__global__ __launch_bounds__(256) void split_f32_kernel(
    const float* __restrict__ x, __nv_bfloat16* __restrict__ hi,
    __nv_bfloat16* __restrict__ lo, int n4)
{
    int i = blockIdx.x * 256 + threadIdx.x;
    if (i >= n4) return;
    float4 v = ((const float4*)x)[i];
    __nv_bfloat16 h0, h1, h2, h3, l0, l1, l2, l3;
    split1(v.x, h0, l0); split1(v.y, h1, l1);
    split1(v.z, h2, l2); split1(v.w, h3, l3);
    ((__nv_bfloat162*)hi)[i * 2]     = __nv_bfloat162(h0, h1);
    ((__nv_bfloat162*)hi)[i * 2 + 1] = __nv_bfloat162(h2, h3);
    ((__nv_bfloat162*)lo)[i * 2]     = __nv_bfloat162(l0, l1);
    ((__nv_bfloat162*)lo)[i * 2 + 1] = __nv_bfloat162(l2, l3);
}

// W [1024(K), N] fp32 -> [N][1024] bf16 hi/lo (transposed)
__global__ __launch_bounds__(256) void transpose_split_kernel(
    const float* __restrict__ W, __nv_bfloat16* __restrict__ hi,
    __nv_bfloat16* __restrict__ lo, int N)
{
    __shared__ float t[32][33];
    const int k0 = blockIdx.y * 32;
    const int n0 = blockIdx.x * 32;
    const int tx = threadIdx.x & 31;
    const int ty = threadIdx.x >> 5;
#pragma unroll
    for (int i = 0; i < 4; i++)
        t[ty + i * 8][tx] = W[(size_t)(k0 + ty + i * 8) * N + n0 + tx];
    __syncthreads();
#pragma unroll
    for (int i = 0; i < 4; i++) {
        int n = n0 + ty + i * 8;
        float v = t[tx][ty + i * 8];
        __nv_bfloat16 h, l;
        split1(v, h, l);
        hi[(size_t)n * 1024 + k0 + tx] = h;
        lo[(size_t)n * 1024 + k0 + tx] = l;
    }
}

// QK fp32 [4096][1024] -> Q or K hi/lo bf16 [bh][2048][32] (blockIdx.y: 0=Q 1=K)
__global__ __launch_bounds__(256) void prep_qk_kernel(
    const float* __restrict__ QK,
    __nv_bfloat16* __restrict__ Qhi, __nv_bfloat16* __restrict__ Qlo,
    __nv_bfloat16* __restrict__ Khi, __nv_bfloat16* __restrict__ Klo)
{
    int idx = blockIdx.x * 256 + threadIdx.x;    // 0 .. 4096*512/4-1
    int row = idx >> 7;
    int q   = idx & 127;
    int h   = q >> 3;
    int r4  = (q & 7) * 4;
    int b   = row >> 11;
    int i   = row & 2047;
    int colbase = blockIdx.y * QKCOLS;
    __nv_bfloat16* hi = blockIdx.y ? Khi : Qhi;
    __nv_bfloat16* lo = blockIdx.y ? Klo : Qlo;
    float4 v = *(const float4*)(QK + (size_t)row * (2 * QKCOLS) + colbase
                                   + h * RANK + r4);
    __nv_bfloat16 h0, h1, h2, h3, l0, l1, l2, l3;
    split1(v.x, h0, l0); split1(v.y, h1, l1);
    split1(v.z, h2, l2); split1(v.w, h3, l3);
    size_t d = ((size_t)(b * NHEAD + h) * S_LEN + i) * RANK + r4;
    ((__nv_bfloat162*)(hi + d))[0] = __nv_bfloat162(h0, h1);
    ((__nv_bfloat162*)(hi + d))[1] = __nv_bfloat162(h2, h3);
    ((__nv_bfloat162*)(lo + d))[0] = __nv_bfloat162(l0, l1);
    ((__nv_bfloat162*)(lo + d))[1] = __nv_bfloat162(l2, l3);
}

// V fp32 [4096][1024] -> Vt hi/lo bf16 [bh][64][2048]
__global__ __launch_bounds__(256) void prep_vt_kernel(
    const float* __restrict__ V, __nv_bfloat16* __restrict__ Vthi,
    __nv_bfloat16* __restrict__ Vtlo)
{
    __shared__ float t[32][33];
    const int j0 = blockIdx.x * 32;
    const int c0 = blockIdx.y * 32;
    const int b  = blockIdx.z;
    const int tx = threadIdx.x & 31;
    const int ty = threadIdx.x >> 5;
#pragma unroll
    for (int i = 0; i < 4; i++)
        t[ty + i * 8][tx] = V[(size_t)(b * S_LEN + j0 + ty + i * 8) * EMBED + c0 + tx];
    __syncthreads();
#pragma unroll
    for (int i = 0; i < 4; i++) {
        int c = c0 + ty + i * 8;
        int h = c >> 6;
        int d = c & 63;
        float v = t[tx][ty + i * 8];
        __nv_bfloat16 vh, vl;
        split1(v, vh, vl);
        size_t o = ((size_t)(b * NHEAD + h) * HDIM + d) * S_LEN + j0 + tx;
        Vthi[o] = vh;
        Vtlo[o] = vl;
    }
}

// ---------------------------------------------------------------------------
// HMMA split-bf16 GEMM: C[M,N] = (Ahi+Alo)[M,1024] @ (Bhi+Blo)[N,1024]^T + bias
// Tiles 128x128x32, cp.async double-buffered, 8 warps (warp tile 32x64).
// SMEM rows: 32 bf16 = 64B payload, 80B stride (conflict-free ldmatrix).
// ---------------------------------------------------------------------------
#define GEMM_STAGE_BYTES 40960
#define GEMM_SMEM_BYTES  (2 * GEMM_STAGE_BYTES)

__global__ __launch_bounds__(256) void hmma_gemm_kernel(
    const __nv_bfloat16* __restrict__ Ahi, const __nv_bfloat16* __restrict__ Alo,
    const __nv_bfloat16* __restrict__ Bhi, const __nv_bfloat16* __restrict__ Blo,
    const float* __restrict__ bias, float* __restrict__ C, int N)
{
    extern __shared__ char sm[];
    const uint32_t sb = smem_u32(sm);

    const int tid = threadIdx.x;
    const int wid = tid >> 5;
    const int lane = tid & 31;
    const int warp_m = wid & 3;
    const int warp_n = wid >> 2;
    const int bm = blockIdx.y * 128;
    const int bn = blockIdx.x * 128;

    const int srow = tid >> 2;
    const int sseg = tid & 3;

    auto issue = [&](int c, int stg) {
        const uint32_t base = sb + stg * GEMM_STAGE_BYTES;
        const size_t kb = (size_t)c * 64;
#pragma unroll
        for (int it = 0; it < 2; it++) {
            int row = srow + it * 64;
            uint32_t so = row * 80 + sseg * 16;
            size_t ga = (size_t)(bm + row) * 2048 + kb + sseg * 16;
            size_t gb = (size_t)(bn + row) * 2048 + kb + sseg * 16;
            cp16(base +     0 + so, (const char*)Ahi + ga);
            cp16(base + 10240 + so, (const char*)Alo + ga);
            cp16(base + 20480 + so, (const char*)Bhi + gb);
            cp16(base + 30720 + so, (const char*)Blo + gb);
        }
    };

    float acc[2][8][4];
#pragma unroll
    for (int mf = 0; mf < 2; mf++)
#pragma unroll
        for (int nf = 0; nf < 8; nf++)
#pragma unroll
            for (int k = 0; k < 4; k++) acc[mf][nf][k] = 0.0f;

    issue(0, 0); cp_commit();
    issue(1, 1); cp_commit();

    for (int c = 0; c < 32; c++) {
        cp_wait<1>();
        __syncthreads();
        const uint32_t base = sb + (c & 1) * GEMM_STAGE_BYTES;

#pragma unroll
        for (int ks = 0; ks < 2; ks++) {
            uint32_t lm_off = (lane & 15) * 80 + ks * 32 + (lane >> 4) * 16;
            uint32_t ah[2][4], al[2][4];
#pragma unroll
            for (int mf = 0; mf < 2; mf++) {
                uint32_t aa = base + (warp_m * 32 + mf * 16) * 80 + lm_off;
                ldm_x4(ah[mf][0], ah[mf][1], ah[mf][2], ah[mf][3], aa);
                ldm_x4(al[mf][0], al[mf][1], al[mf][2], al[mf][3], aa + 10240);
            }
#pragma unroll
            for (int p = 0; p < 4; p++) {
                uint32_t ba = base + 20480 + (warp_n * 64 + p * 16) * 80 + lm_off;
                uint32_t h0, h1, h2, h3, o0, o1, o2, o3;
                ldm_x4(h0, h1, h2, h3, ba);
                ldm_x4(o0, o1, o2, o3, ba + 10240);
#pragma unroll
                for (int mf = 0; mf < 2; mf++) {
                    mma_bf16(acc[mf][2 * p],     ah[mf], h0, h2);
                    mma_bf16(acc[mf][2 * p],     ah[mf], o0, o2);
                    mma_bf16(acc[mf][2 * p],     al[mf], h0, h2);
                    mma_bf16(acc[mf][2 * p + 1], ah[mf], h1, h3);
                    mma_bf16(acc[mf][2 * p + 1], ah[mf], o1, o3);
                    mma_bf16(acc[mf][2 * p + 1], al[mf], h1, h3);
                }
            }
        }
        __syncthreads();
        if (c + 2 < 32) issue(c + 2, c & 1);
        cp_commit();   // always commit (keeps wait-group accounting exact)
    }

    // Epilogue: direct float2 stores with bias
#pragma unroll
    for (int mf = 0; mf < 2; mf++) {
        int row0 = bm + warp_m * 32 + mf * 16 + (lane >> 2);
#pragma unroll
        for (int nf = 0; nf < 8; nf++) {
            int col = bn + warp_n * 64 + nf * 8 + 2 * (lane & 3);
            float b0 = bias[col], b1 = bias[col + 1];
            float2 v0 = make_float2(acc[mf][nf][0] + b0, acc[mf][nf][1] + b1);
            float2 v1 = make_float2(acc[mf][nf][2] + b0, acc[mf][nf][3] + b1);
            *(float2*)(C + (size_t)row0 * N + col)       = v0;
            *(float2*)(C + (size_t)(row0 + 8) * N + col) = v1;
        }
    }
}

// ---------------------------------------------------------------------------
// HMMA flash attention (split-precision, 2-stage: 2 CTAs/SM).
// Grid (S/128, BH), 256 threads (8 warps, 16 q-rows each).
// SMEM: Q hi/lo 20480; 2 stages x (Khi 5120 | Klo 5120 | Vhi 8192 | Vlo 8192)
// ---------------------------------------------------------------------------
#define ATT_Q_BYTES     20480
#define ATT_STAGE_BYTES 26624
#define ATT_SMEM_BYTES  (ATT_Q_BYTES + 2 * ATT_STAGE_BYTES)   // 73728
#define ATT_SCALE       0.17677669529663687f

__global__ __launch_bounds__(256) void attn_hmma_kernel(
    const __nv_bfloat16* __restrict__ Qhi, const __nv_bfloat16* __restrict__ Qlo,
    const __nv_bfloat16* __restrict__ Khi, const __nv_bfloat16* __restrict__ Klo,
    const __nv_bfloat16* __restrict__ Vthi, const __nv_bfloat16* __restrict__ Vtlo,
    float* __restrict__ AO)
{
    extern __shared__ char sm[];
    const uint32_t sb = smem_u32(sm);

    const int tid  = threadIdx.x;
    const int wid  = tid >> 5;
    const int lane = tid & 31;
    const int bh = blockIdx.y;
    const int b = bh >> 4, h = bh & 15;
    const int i0 = blockIdx.x * 128;

    // Load Q tile (hi/lo) once: 128 rows x 64B -> 80B-stride smem
    {
        const char* qh = (const char*)(Qhi + ((size_t)bh * S_LEN + i0) * RANK);
        const char* ql = (const char*)(Qlo + ((size_t)bh * S_LEN + i0) * RANK);
#pragma unroll
        for (int it = 0; it < 2; it++) {
            int idx = tid + it * 256;
            int row = idx >> 2, seg = idx & 3;
            uint32_t so = row * 80 + seg * 16;
            size_t go = (size_t)row * 64 + seg * 16;
            *(uint4*)(sm + so)         = *(const uint4*)(qh + go);
            *(uint4*)(sm + 10240 + so) = *(const uint4*)(ql + go);
        }
    }

    auto issue = [&](int jt, int stg) {
        const uint32_t base = sb + ATT_Q_BYTES + stg * ATT_STAGE_BYTES;
        {
            int row = tid >> 2, seg = tid & 3;
            size_t go = ((size_t)bh * S_LEN + jt * 64 + row) * 64 + seg * 16;
            uint32_t so = row * 80 + seg * 16;
            cp16(base + so,        (const char*)Khi + go);
            cp16(base + 5120 + so, (const char*)Klo + go);
        }
        const size_t vbase = (size_t)bh * HDIM * S_LEN + jt * 64;
        const char* vh = (const char*)(Vthi + vbase);
        const char* vl = (const char*)(Vtlo + vbase);
#pragma unroll
        for (int it = 0; it < 2; it++) {
            int idx = tid + it * 256;
            int d = idx >> 3, seg = idx & 7;
            uint32_t so = d * 128 + ((seg ^ (d & 7)) * 16);
            size_t go = (size_t)d * (S_LEN * 2) + seg * 16;
            cp16(base + 10240 + so, vh + go);
            cp16(base + 18432 + so, vl + go);
        }
    };

    float m0 = -1e30f, m1 = -1e30f, l0 = 0.0f, l1 = 0.0f;
    float o[8][4];
#pragma unroll
    for (int nf = 0; nf < 8; nf++)
#pragma unroll
        for (int k = 0; k < 4; k++) o[nf][k] = 0.0f;

    issue(0, 0); cp_commit();
    issue(1, 1); cp_commit();

    const int NJT = S_LEN / 64;   // 32
    for (int jt = 0; jt < NJT; jt++) {
        cp_wait<1>();
        __syncthreads();
        const uint32_t base = sb + ATT_Q_BYTES + (jt & 1) * ATT_STAGE_BYTES;

        // ---- S = Q K^T (split, 3-term) ----
        float s[8][4];
#pragma unroll
        for (int nf = 0; nf < 8; nf++)
#pragma unroll
            for (int k = 0; k < 4; k++) s[nf][k] = 0.0f;

#pragma unroll
        for (int ks = 0; ks < 2; ks++) {
            uint32_t lm_off = (lane & 15) * 80 + ks * 32 + (lane >> 4) * 16;
            uint32_t qh[4], ql[4];
            uint32_t qa = sb + (wid * 16) * 80 + lm_off;
            ldm_x4(qh[0], qh[1], qh[2], qh[3], qa);
            ldm_x4(ql[0], ql[1], ql[2], ql[3], qa + 10240);
#pragma unroll
            for (int p = 0; p < 4; p++) {
                uint32_t ka = base + (p * 16) * 80 + lm_off;
                uint32_t h0, h1, h2, h3, o0, o1, o2, o3;
                ldm_x4(h0, h1, h2, h3, ka);
                ldm_x4(o0, o1, o2, o3, ka + 5120);
                mma_bf16(s[2 * p],     qh, h0, h2);
                mma_bf16(s[2 * p],     qh, o0, o2);
                mma_bf16(s[2 * p],     ql, h0, h2);
                mma_bf16(s[2 * p + 1], qh, h1, h3);
                mma_bf16(s[2 * p + 1], qh, o1, o3);
                mma_bf16(s[2 * p + 1], ql, h1, h3);
            }
        }

        // ---- online softmax (fp32) ----
        float mx0 = -1e30f, mx1 = -1e30f;
#pragma unroll
        for (int nf = 0; nf < 8; nf++) {
            mx0 = fmaxf(mx0, fmaxf(s[nf][0], s[nf][1]));
            mx1 = fmaxf(mx1, fmaxf(s[nf][2], s[nf][3]));
        }
#pragma unroll
        for (int off = 1; off <= 2; off <<= 1) {
            mx0 = fmaxf(mx0, __shfl_xor_sync(0xffffffffu, mx0, off));
            mx1 = fmaxf(mx1, __shfl_xor_sync(0xffffffffu, mx1, off));
        }
        mx0 *= ATT_SCALE; mx1 *= ATT_SCALE;
        float nm0 = fmaxf(m0, mx0), nm1 = fmaxf(m1, mx1);
        float al0 = __expf(m0 - nm0), al1 = __expf(m1 - nm1);
        m0 = nm0; m1 = nm1;

        float sum0 = 0.0f, sum1 = 0.0f;
#pragma unroll
        for (int nf = 0; nf < 8; nf++) {
            s[nf][0] = __expf(s[nf][0] * ATT_SCALE - nm0);
            s[nf][1] = __expf(s[nf][1] * ATT_SCALE - nm0);
            s[nf][2] = __expf(s[nf][2] * ATT_SCALE - nm1);
            s[nf][3] = __expf(s[nf][3] * ATT_SCALE - nm1);
            sum0 += s[nf][0] + s[nf][1];
            sum1 += s[nf][2] + s[nf][3];
        }
        l0 = l0 * al0 + sum0;
        l1 = l1 * al1 + sum1;
#pragma unroll
        for (int nf = 0; nf < 8; nf++) {
            o[nf][0] *= al0; o[nf][1] *= al0;
            o[nf][2] *= al1; o[nf][3] *= al1;
        }

        // ---- pack P (hi + residual lo) as A-fragments ----
        uint32_t ph[4][4], pl[4][4];
#pragma unroll
        for (int kf = 0; kf < 4; kf++) {
            split_pack2(s[2 * kf][0],     s[2 * kf][1],     ph[kf][0], pl[kf][0]);
            split_pack2(s[2 * kf][2],     s[2 * kf][3],     ph[kf][1], pl[kf][1]);
            split_pack2(s[2 * kf + 1][0], s[2 * kf + 1][1], ph[kf][2], pl[kf][2]);
            split_pack2(s[2 * kf + 1][2], s[2 * kf + 1][3], ph[kf][3], pl[kf][3]);
        }

        // ---- O += P @ V  (3-term split) ----
#pragma unroll
        for (int kf = 0; kf < 4; kf++) {
#pragma unroll
            for (int pd = 0; pd < 4; pd++) {
                int d = pd * 16 + (lane & 15);
                int seg = kf * 2 + (lane >> 4);
                uint32_t so = d * 128 + ((seg ^ (d & 7)) * 16);
                uint32_t vh0, vh1, vh2, vh3, vl0, vl1, vl2, vl3;
                ldm_x4(vh0, vh1, vh2, vh3, base + 10240 + so);
                ldm_x4(vl0, vl1, vl2, vl3, base + 18432 + so);
                mma_bf16(o[2 * pd],     ph[kf], vh0, vh2);
                mma_bf16(o[2 * pd],     ph[kf], vl0, vl2);
                mma_bf16(o[2 * pd],     pl[kf], vh0, vh2);
                mma_bf16(o[2 * pd + 1], ph[kf], vh1, vh3);
                mma_bf16(o[2 * pd + 1], ph[kf], vl1, vl3);
                mma_bf16(o[2 * pd + 1], pl[kf], vh1, vh3);
            }
        }

        __syncthreads();
        if (jt + 2 < NJT) issue(jt + 2, jt & 1);
        cp_commit();   // always commit
    }

    // ---- epilogue: normalize, write AO (fp32) ----
#pragma unroll
    for (int off = 1; off <= 2; off <<= 1) {
        l0 += __shfl_xor_sync(0xffffffffu, l0, off);
        l1 += __shfl_xor_sync(0xffffffffu, l1, off);
    }
    float inv0 = 1.0f / l0, inv1 = 1.0f / l1;

    int row0 = b * S_LEN + i0 + wid * 16 + (lane >> 2);
#pragma unroll
    for (int nf = 0; nf < 8; nf++) {
        int col = h * HDIM + nf * 8 + 2 * (lane & 3);
        *(float2*)(AO + (size_t)row0 * EMBED + col) =
            make_float2(o[nf][0] * inv0, o[nf][1] * inv0);
        *(float2*)(AO + (size_t)(row0 + 8) * EMBED + col) =
            make_float2(o[nf][2] * inv1, o[nf][3] * inv1);
    }
}

// ---------------------------------------------------------------------------
// Launch
// ---------------------------------------------------------------------------
extern "C" void kernel_launch(void* const* d_in, const int* in_sizes, int n_in,
                              void* d_out, int out_size)
{
    const float* X  = (const float*)d_in[0];
    const float* Wq = (const float*)d_in[1];
    const float* bq = (const float*)d_in[2];
    const float* Wk = (const float*)d_in[3];
    const float* bk = (const float*)d_in[4];
    const float* Wv = (const float*)d_in[5];
    const float* bv = (const float*)d_in[6];
    const float* Wo = (const float*)d_in[7];
    const float* bo = (const float*)d_in[8];
    float* out = (float*)d_out;

    float *QKp, *Vp, *AOp, *bqk;
    cudaGetSymbolAddress((void**)&QKp, g_QK);
    cudaGetSymbolAddress((void**)&Vp,  g_V);
    cudaGetSymbolAddress((void**)&AOp, g_AO);
    cudaGetSymbolAddress((void**)&bqk, g_bqk);

    __nv_bfloat16 *Xhi, *Xlo, *AOhi, *AOlo;
    __nv_bfloat16 *Wqkh, *Wqkl, *Wvh, *Wvl, *Woh, *Wol;
    __nv_bfloat16 *Qhi, *Qlo, *Khi, *Klo, *Vth, *Vtl;
    cudaGetSymbolAddress((void**)&Xhi,  g_Xhi);
    cudaGetSymbolAddress((void**)&Xlo,  g_Xlo);
    cudaGetSymbolAddress((void**)&AOhi, g_AOhi);
    cudaGetSymbolAddress((void**)&AOlo, g_AOlo);
    cudaGetSymbolAddress((void**)&Wqkh, g_Wqk_hi);
    cudaGetSymbolAddress((void**)&Wqkl, g_Wqk_lo);
    cudaGetSymbolAddress((void**)&Wvh,  g_Wv_hi);
    cudaGetSymbolAddress((void**)&Wvl,  g_Wv_lo);
    cudaGetSymbolAddress((void**)&Woh,  g_Wo_hi);
    cudaGetSymbolAddress((void**)&Wol,  g_Wo_lo);
    cudaGetSymbolAddress((void**)&Qhi,  g_Qhi);
    cudaGetSymbolAddress((void**)&Qlo,  g_Qlo);
    cudaGetSymbolAddress((void**)&Khi,  g_Khi);
    cudaGetSymbolAddress((void**)&Klo,  g_Klo);
    cudaGetSymbolAddress((void**)&Vth,  g_Vthi);
    cudaGetSymbolAddress((void**)&Vtl,  g_Vtlo);

    cudaFuncSetAttribute(hmma_gemm_kernel,
                         cudaFuncAttributeMaxDynamicSharedMemorySize,
                         GEMM_SMEM_BYTES);
    cudaFuncSetAttribute(attn_hmma_kernel,
                         cudaFuncAttributeMaxDynamicSharedMemorySize,
                         ATT_SMEM_BYTES);

    const int nX4 = MROWS * EMBED / 4;

    // 1) input conversions + combined QK weight/bias
    split_f32_kernel<<<(nX4 + 255) / 256, 256>>>(X, Xhi, Xlo, nX4);
    transpose_split_kernel<<<dim3(QKCOLS / 32, EMBED / 32), 256>>>(Wq, Wqkh, Wqkl, QKCOLS);
    transpose_split_kernel<<<dim3(QKCOLS / 32, EMBED / 32), 256>>>(
        Wk, Wqkh + (size_t)QKCOLS * EMBED, Wqkl + (size_t)QKCOLS * EMBED, QKCOLS);
    transpose_split_kernel<<<dim3(EMBED / 32, EMBED / 32), 256>>>(Wv, Wvh, Wvl, EMBED);
    transpose_split_kernel<<<dim3(EMBED / 32, EMBED / 32), 256>>>(Wo, Woh, Wol, EMBED);
    cudaMemcpyAsync(bqk,          bq, QKCOLS * sizeof(float), cudaMemcpyDeviceToDevice);
    cudaMemcpyAsync(bqk + QKCOLS, bk, QKCOLS * sizeof(float), cudaMemcpyDeviceToDevice);

    // 2) projections: fused QK GEMM + V GEMM
    hmma_gemm_kernel<<<dim3(2 * QKCOLS / 128, MROWS / 128), 256, GEMM_SMEM_BYTES>>>(
        Xhi, Xlo, Wqkh, Wqkl, bqk, QKp, 2 * QKCOLS);
    hmma_gemm_kernel<<<dim3(EMBED / 128, MROWS / 128), 256, GEMM_SMEM_BYTES>>>(
        Xhi, Xlo, Wvh, Wvl, bv, Vp, EMBED);

    // 3) attention prep (Q and K in one launch; Vt transpose)
    prep_qk_kernel<<<dim3(MROWS * QKCOLS / 4 / 256, 2), 256>>>(QKp, Qhi, Qlo, Khi, Klo);
    prep_vt_kernel<<<dim3(S_LEN / 32, EMBED / 32, BATCH), 256>>>(Vp, Vth, Vtl);

    // 4) attention (HMMA flash, split-precision)
    attn_hmma_kernel<<<dim3(S_LEN / 128, BH), 256, ATT_SMEM_BYTES>>>(
        Qhi, Qlo, Khi, Klo, Vth, Vtl, AOp);

    // 5) output projection
    split_f32_kernel<<<(nX4 + 255) / 256, 256>>>(AOp, AOhi, AOlo, nX4);
    hmma_gemm_kernel<<<dim3(EMBED / 128, MROWS / 128), 256, GEMM_SMEM_BYTES>>>(
        AOhi, AOlo, Woh, Wol, bo, out, EMBED);
}

// round 15
// speedup vs baseline: 3.2253x; 3.2253x over previous
#include <cuda_runtime.h>
#include <cuda_fp16.h>
#include <cstdint>

// Problem constants
#define S_LEN  2048
#define BATCH  2
#define EMBED  1024
#define NHEAD  16
#define RANK   32
#define HDIM   64
#define MROWS  (BATCH * S_LEN)   // 4096
#define QKCOLS (NHEAD * RANK)    // 512
#define BH     (BATCH * NHEAD)   // 32

// ---------------------------------------------------------------------------
// Scratch (__device__ globals)
// ---------------------------------------------------------------------------
__device__ float g_QK[MROWS * 2 * QKCOLS];   // fused Q|K fp32 [4096][1024]
__device__ float g_V [MROWS * EMBED];
__device__ float g_AO[MROWS * EMBED];
__device__ float g_bqk[2 * QKCOLS];

__device__ __half g_X16 [MROWS * EMBED];
__device__ __half g_AO16[MROWS * EMBED];
__device__ __half g_Wqk16[2 * QKCOLS * EMBED];  // [N=1024][K=1024] (Wq rows 0-511)
__device__ __half g_Wv16[EMBED * EMBED];
__device__ __half g_Wo16[EMBED * EMBED];

// Attention-layout tensors
__device__ __half g_Q16[MROWS * QKCOLS];        // [bh][S][32]
__device__ __half g_K16[MROWS * QKCOLS];
__device__ __half g_Vt16[BH * HDIM * S_LEN];    // [bh][d][S]

// ---------------------------------------------------------------------------
// Helpers (compute_103-safe: mma.sync / ldmatrix / cp.async only)
// ---------------------------------------------------------------------------
__device__ __forceinline__ uint32_t smem_u32(const void* p) {
    uint32_t a;
    asm("{ .reg .u64 t; cvta.to.shared.u64 t, %1; cvt.u32.u64 %0, t; }"
        : "=r"(a) : "l"(p));
    return a;
}

__device__ __forceinline__ void cp16(uint32_t dst, const void* src) {
    asm volatile("cp.async.cg.shared.global [%0], [%1], 16;"
                 :: "r"(dst), "l"(src) : "memory");
}
__device__ __forceinline__ void cp_commit() {
    asm volatile("cp.async.commit_group;" ::: "memory");
}
template<int N> __device__ __forceinline__ void cp_wait() {
    asm volatile("cp.async.wait_group %0;" :: "n"(N) : "memory");
}

__device__ __forceinline__ void ldm_x4(uint32_t& r0, uint32_t& r1,
                                       uint32_t& r2, uint32_t& r3, uint32_t a) {
    asm volatile("ldmatrix.sync.aligned.m8n8.x4.shared.b16 {%0,%1,%2,%3}, [%4];"
                 : "=r"(r0), "=r"(r1), "=r"(r2), "=r"(r3) : "r"(a));
}

__device__ __forceinline__ void mma_f16(float c[4], const uint32_t a[4],
                                        uint32_t b0, uint32_t b1) {
    asm volatile(
        "mma.sync.aligned.m16n8k16.row.col.f32.f16.f16.f32 "
        "{%0,%1,%2,%3}, {%4,%5,%6,%7}, {%8,%9}, {%0,%1,%2,%3};"
        : "+f"(c[0]), "+f"(c[1]), "+f"(c[2]), "+f"(c[3])
        : "r"(a[0]), "r"(a[1]), "r"(a[2]), "r"(a[3]), "r"(b0), "r"(b1));
}

__device__ __forceinline__ uint32_t pack_h2(float a, float b) {
    __half2 t = __floats2half2_rn(a, b);
    return *(uint32_t*)&t;
}

// ---------------------------------------------------------------------------
// Conversion kernels
// ---------------------------------------------------------------------------
__global__ __launch_bounds__(256) void f32_to_f16_kernel(
    const float* __restrict__ x, __half* __restrict__ y, int n4)
{
    int i = blockIdx.x * 256 + threadIdx.x;
    if (i >= n4) return;
    float4 v = ((const float4*)x)[i];
    ((__half2*)y)[i * 2]     = __floats2half2_rn(v.x, v.y);
    ((__half2*)y)[i * 2 + 1] = __floats2half2_rn(v.z, v.w);
}

// W [1024(K), N] fp32 -> [N][1024] fp16 (transposed)
__global__ __launch_bounds__(256) void transpose_f16_kernel(
    const float* __restrict__ W, __half* __restrict__ Wt, int N)
{
    __shared__ float t[32][33];
    const int k0 = blockIdx.y * 32;
    const int n0 = blockIdx.x * 32;
    const int tx = threadIdx.x & 31;
    const int ty = threadIdx.x >> 5;
#pragma unroll
    for (int i = 0; i < 4; i++)
        t[ty + i * 8][tx] = W[(size_t)(k0 + ty + i * 8) * N + n0 + tx];
    __syncthreads();
#pragma unroll
    for (int i = 0; i < 4; i++) {
        int n = n0 + ty + i * 8;
        Wt[(size_t)n * 1024 + k0 + tx] = __float2half_rn(t[tx][ty + i * 8]);
    }
}

// QK fp32 [4096][1024] -> Q or K fp16 [bh][2048][32] (blockIdx.y: 0=Q 1=K)
__global__ __launch_bounds__(256) void prep_qk_kernel(
    const float* __restrict__ QK,
    __half* __restrict__ Q16, __half* __restrict__ K16)
{
    int idx = blockIdx.x * 256 + threadIdx.x;
    int row = idx >> 7;
    int q   = idx & 127;
    int h   = q >> 3;
    int r4  = (q & 7) * 4;
    int b   = row >> 11;
    int i   = row & 2047;
    __half* dstp = blockIdx.y ? K16 : Q16;
    float4 v = *(const float4*)(QK + (size_t)row * (2 * QKCOLS)
                                   + blockIdx.y * QKCOLS + h * RANK + r4);
    size_t d = ((size_t)(b * NHEAD + h) * S_LEN + i) * RANK + r4;
    ((__half2*)(dstp + d))[0] = __floats2half2_rn(v.x, v.y);
    ((__half2*)(dstp + d))[1] = __floats2half2_rn(v.z, v.w);
}

// V fp32 [4096][1024] -> Vt fp16 [bh][64][2048]
__global__ __launch_bounds__(256) void prep_vt_kernel(
    const float* __restrict__ V, __half* __restrict__ Vt)
{
    __shared__ float t[32][33];
    const int j0 = blockIdx.x * 32;
    const int c0 = blockIdx.y * 32;
    const int b  = blockIdx.z;
    const int tx = threadIdx.x & 31;
    const int ty = threadIdx.x >> 5;
#pragma unroll
    for (int i = 0; i < 4; i++)
        t[ty + i * 8][tx] = V[(size_t)(b * S_LEN + j0 + ty + i * 8) * EMBED + c0 + tx];
    __syncthreads();
#pragma unroll
    for (int i = 0; i < 4; i++) {
        int c = c0 + ty + i * 8;
        int h = c >> 6;
        int d = c & 63;
        Vt[((size_t)(b * NHEAD + h) * HDIM + d) * S_LEN + j0 + tx] =
            __float2half_rn(t[tx][ty + i * 8]);
    }
}

// ---------------------------------------------------------------------------
// fp16 single-term HMMA GEMM: C[M,N] = A[M,1024] @ B[N,1024]^T + bias
// Tiles 128x128x32, cp.async double-buffered, 8 warps (warp tile 32x64).
// SMEM rows: 32 fp16 = 64B payload @ 80B stride (conflict-free ldmatrix).
// ---------------------------------------------------------------------------
#define GEMM_STAGE_BYTES 20480   // A 10240 + B 10240
#define GEMM_SMEM_BYTES  (2 * GEMM_STAGE_BYTES)   // 40960

__global__ __launch_bounds__(256) void hmma_gemm_kernel(
    const __half* __restrict__ A, const __half* __restrict__ B,
    const float* __restrict__ bias, float* __restrict__ C, int N)
{
    extern __shared__ char sm[];
    const uint32_t sb = smem_u32(sm);

    const int tid = threadIdx.x;
    const int wid = tid >> 5;
    const int lane = tid & 31;
    const int warp_m = wid & 3;
    const int warp_n = wid >> 2;
    const int bm = blockIdx.y * 128;
    const int bn = blockIdx.x * 128;

    const int srow = tid >> 2;     // 64 rows x 4 segs per pass
    const int sseg = tid & 3;

    auto issue = [&](int c, int stg) {
        const uint32_t base = sb + stg * GEMM_STAGE_BYTES;
        const size_t kb = (size_t)c * 64;
#pragma unroll
        for (int it = 0; it < 2; it++) {
            int row = srow + it * 64;
            uint32_t so = row * 80 + sseg * 16;
            cp16(base + so,
                 (const char*)A + (size_t)(bm + row) * 2048 + kb + sseg * 16);
            cp16(base + 10240 + so,
                 (const char*)B + (size_t)(bn + row) * 2048 + kb + sseg * 16);
        }
    };

    float acc[2][8][4];
#pragma unroll
    for (int mf = 0; mf < 2; mf++)
#pragma unroll
        for (int nf = 0; nf < 8; nf++)
#pragma unroll
            for (int k = 0; k < 4; k++) acc[mf][nf][k] = 0.0f;

    issue(0, 0); cp_commit();
    issue(1, 1); cp_commit();

    for (int c = 0; c < 32; c++) {
        cp_wait<1>();
        __syncthreads();
        const uint32_t base = sb + (c & 1) * GEMM_STAGE_BYTES;

#pragma unroll
        for (int ks = 0; ks < 2; ks++) {
            uint32_t lm_off = (lane & 15) * 80 + ks * 32 + (lane >> 4) * 16;
            uint32_t a[2][4];
#pragma unroll
            for (int mf = 0; mf < 2; mf++) {
                uint32_t aa = base + (warp_m * 32 + mf * 16) * 80 + lm_off;
                ldm_x4(a[mf][0], a[mf][1], a[mf][2], a[mf][3], aa);
            }
#pragma unroll
            for (int p = 0; p < 4; p++) {
                uint32_t ba = base + 10240 + (warp_n * 64 + p * 16) * 80 + lm_off;
                uint32_t h0, h1, h2, h3;
                ldm_x4(h0, h1, h2, h3, ba);
#pragma unroll
                for (int mf = 0; mf < 2; mf++) {
                    mma_f16(acc[mf][2 * p],     a[mf], h0, h2);
                    mma_f16(acc[mf][2 * p + 1], a[mf], h1, h3);
                }
            }
        }
        __syncthreads();
        if (c + 2 < 32) issue(c + 2, c & 1);
        cp_commit();   // always commit (keeps wait-group accounting exact)
    }

    // Epilogue: direct float2 stores with bias
#pragma unroll
    for (int mf = 0; mf < 2; mf++) {
        int row0 = bm + warp_m * 32 + mf * 16 + (lane >> 2);
#pragma unroll
        for (int nf = 0; nf < 8; nf++) {
            int col = bn + warp_n * 64 + nf * 8 + 2 * (lane & 3);
            float b0 = bias[col], b1 = bias[col + 1];
            float2 v0 = make_float2(acc[mf][nf][0] + b0, acc[mf][nf][1] + b1);
            float2 v1 = make_float2(acc[mf][nf][2] + b0, acc[mf][nf][3] + b1);
            *(float2*)(C + (size_t)row0 * N + col)       = v0;
            *(float2*)(C + (size_t)(row0 + 8) * N + col) = v1;
        }
    }
}

// ---------------------------------------------------------------------------
// fp16 flash attention. Grid (S/128, BH), 256 threads (8 warps, 16 q-rows).
// SMEM: Q 10240; 2 stages x (K 5120 | Vt 8192) = 36864 total.
// ---------------------------------------------------------------------------
#define ATT_Q_BYTES     10240
#define ATT_STAGE_BYTES 13312
#define ATT_SMEM_BYTES  (ATT_Q_BYTES + 2 * ATT_STAGE_BYTES)   // 36864
#define ATT_SCALE       0.17677669529663687f

__global__ __launch_bounds__(256) void attn_hmma_kernel(
    const __half* __restrict__ Q16, const __half* __restrict__ K16,
    const __half* __restrict__ Vt16, float* __restrict__ AO)
{
    extern __shared__ char sm[];
    const uint32_t sb = smem_u32(sm);

    const int tid  = threadIdx.x;
    const int wid  = tid >> 5;
    const int lane = tid & 31;
    const int bh = blockIdx.y;
    const int b = bh >> 4, h = bh & 15;
    const int i0 = blockIdx.x * 128;

    // Load Q tile once: 128 rows x 64B -> 80B-stride smem
    {
        const char* qp = (const char*)(Q16 + ((size_t)bh * S_LEN + i0) * RANK);
#pragma unroll
        for (int it = 0; it < 2; it++) {
            int idx = tid + it * 256;
            int row = idx >> 2, seg = idx & 3;
            *(uint4*)(sm + row * 80 + seg * 16) =
                *(const uint4*)(qp + (size_t)row * 64 + seg * 16);
        }
    }

    auto issue = [&](int jt, int stg) {
        const uint32_t base = sb + ATT_Q_BYTES + stg * ATT_STAGE_BYTES;
        {
            int row = tid >> 2, seg = tid & 3;
            cp16(base + row * 80 + seg * 16,
                 (const char*)K16 + ((size_t)bh * S_LEN + jt * 64 + row) * 64
                                  + seg * 16);
        }
        const char* vp = (const char*)(Vt16 + (size_t)bh * HDIM * S_LEN + jt * 64);
#pragma unroll
        for (int it = 0; it < 2; it++) {
            int idx = tid + it * 256;
            int d = idx >> 3, seg = idx & 7;
            cp16(base + 5120 + d * 128 + ((seg ^ (d & 7)) * 16),
                 vp + (size_t)d * (S_LEN * 2) + seg * 16);
        }
    };

    float m0 = -1e30f, m1 = -1e30f, l0 = 0.0f, l1 = 0.0f;
    float o[8][4];
#pragma unroll
    for (int nf = 0; nf < 8; nf++)
#pragma unroll
        for (int k = 0; k < 4; k++) o[nf][k] = 0.0f;

    issue(0, 0); cp_commit();
    issue(1, 1); cp_commit();

    const int NJT = S_LEN / 64;   // 32
    for (int jt = 0; jt < NJT; jt++) {
        cp_wait<1>();
        __syncthreads();
        const uint32_t base = sb + ATT_Q_BYTES + (jt & 1) * ATT_STAGE_BYTES;

        // ---- S = Q K^T ----
        float s[8][4];
#pragma unroll
        for (int nf = 0; nf < 8; nf++)
#pragma unroll
            for (int k = 0; k < 4; k++) s[nf][k] = 0.0f;

#pragma unroll
        for (int ks = 0; ks < 2; ks++) {
            uint32_t lm_off = (lane & 15) * 80 + ks * 32 + (lane >> 4) * 16;
            uint32_t q[4];
            ldm_x4(q[0], q[1], q[2], q[3], sb + (wid * 16) * 80 + lm_off);
#pragma unroll
            for (int p = 0; p < 4; p++) {
                uint32_t h0, h1, h2, h3;
                ldm_x4(h0, h1, h2, h3, base + (p * 16) * 80 + lm_off);
                mma_f16(s[2 * p],     q, h0, h2);
                mma_f16(s[2 * p + 1], q, h1, h3);
            }
        }

        // ---- online softmax (fp32) ----
        float mx0 = -1e30f, mx1 = -1e30f;
#pragma unroll
        for (int nf = 0; nf < 8; nf++) {
            mx0 = fmaxf(mx0, fmaxf(s[nf][0], s[nf][1]));
            mx1 = fmaxf(mx1, fmaxf(s[nf][2], s[nf][3]));
        }
#pragma unroll
        for (int off = 1; off <= 2; off <<= 1) {
            mx0 = fmaxf(mx0, __shfl_xor_sync(0xffffffffu, mx0, off));
            mx1 = fmaxf(mx1, __shfl_xor_sync(0xffffffffu, mx1, off));
        }
        mx0 *= ATT_SCALE; mx1 *= ATT_SCALE;
        float nm0 = fmaxf(m0, mx0), nm1 = fmaxf(m1, mx1);
        float al0 = __expf(m0 - nm0), al1 = __expf(m1 - nm1);
        m0 = nm0; m1 = nm1;

        float sum0 = 0.0f, sum1 = 0.0f;
#pragma unroll
        for (int nf = 0; nf < 8; nf++) {
            s[nf][0] = __expf(s[nf][0] * ATT_SCALE - nm0);
            s[nf][1] = __expf(s[nf][1] * ATT_SCALE - nm0);
            s[nf][2] = __expf(s[nf][2] * ATT_SCALE - nm1);
            s[nf][3] = __expf(s[nf][3] * ATT_SCALE - nm1);
            sum0 += s[nf][0] + s[nf][1];
            sum1 += s[nf][2] + s[nf][3];
        }
        l0 = l0 * al0 + sum0;
        l1 = l1 * al1 + sum1;
#pragma unroll
        for (int nf = 0; nf < 8; nf++) {
            o[nf][0] *= al0; o[nf][1] *= al0;
            o[nf][2] *= al1; o[nf][3] *= al1;
        }

        // ---- pack P as fp16 A-fragments ----
        uint32_t pf[4][4];
#pragma unroll
        for (int kf = 0; kf < 4; kf++) {
            pf[kf][0] = pack_h2(s[2 * kf][0],     s[2 * kf][1]);
            pf[kf][1] = pack_h2(s[2 * kf][2],     s[2 * kf][3]);
            pf[kf][2] = pack_h2(s[2 * kf + 1][0], s[2 * kf + 1][1]);
            pf[kf][3] = pack_h2(s[2 * kf + 1][2], s[2 * kf + 1][3]);
        }

        // ---- O += P @ V ----
#pragma unroll
        for (int kf = 0; kf < 4; kf++) {
#pragma unroll
            for (int pd = 0; pd < 4; pd++) {
                int d = pd * 16 + (lane & 15);
                int seg = kf * 2 + (lane >> 4);
                uint32_t va = base + 5120 + d * 128 + ((seg ^ (d & 7)) * 16);
                uint32_t v0, v1, v2, v3;
                ldm_x4(v0, v1, v2, v3, va);
                mma_f16(o[2 * pd],     pf[kf], v0, v2);
                mma_f16(o[2 * pd + 1], pf[kf], v1, v3);
            }
        }

        __syncthreads();
        if (jt + 2 < NJT) issue(jt + 2, jt & 1);
        cp_commit();   // always commit
    }

    // ---- epilogue: normalize, write AO (fp32) ----
#pragma unroll
    for (int off = 1; off <= 2; off <<= 1) {
        l0 += __shfl_xor_sync(0xffffffffu, l0, off);
        l1 += __shfl_xor_sync(0xffffffffu, l1, off);
    }
    float inv0 = 1.0f / l0, inv1 = 1.0f / l1;

    int row0 = b * S_LEN + i0 + wid * 16 + (lane >> 2);
#pragma unroll
    for (int nf = 0; nf < 8; nf++) {
        int col = h * HDIM + nf * 8 + 2 * (lane & 3);
        *(float2*)(AO + (size_t)row0 * EMBED + col) =
            make_float2(o[nf][0] * inv0, o[nf][1] * inv0);
        *(float2*)(AO + (size_t)(row0 + 8) * EMBED + col) =
            make_float2(o[nf][2] * inv1, o[nf][3] * inv1);
    }
}

// ---------------------------------------------------------------------------
// Launch
// ---------------------------------------------------------------------------
extern "C" void kernel_launch(void* const* d_in, const int* in_sizes, int n_in,
                              void* d_out, int out_size)
{
    const float* X  = (const float*)d_in[0];
    const float* Wq = (const float*)d_in[1];
    const float* bq = (const float*)d_in[2];
    const float* Wk = (const float*)d_in[3];
    const float* bk = (const float*)d_in[4];
    const float* Wv = (const float*)d_in[5];
    const float* bv = (const float*)d_in[6];
    const float* Wo = (const float*)d_in[7];
    const float* bo = (const float*)d_in[8];
    float* out = (float*)d_out;

    float *QKp, *Vp, *AOp, *bqk;
    cudaGetSymbolAddress((void**)&QKp, g_QK);
    cudaGetSymbolAddress((void**)&Vp,  g_V);
    cudaGetSymbolAddress((void**)&AOp, g_AO);
    cudaGetSymbolAddress((void**)&bqk, g_bqk);

    __half *X16, *AO16, *Wqk16, *Wv16, *Wo16, *Q16, *K16, *Vt16;
    cudaGetSymbolAddress((void**)&X16,   g_X16);
    cudaGetSymbolAddress((void**)&AO16,  g_AO16);
    cudaGetSymbolAddress((void**)&Wqk16, g_Wqk16);
    cudaGetSymbolAddress((void**)&Wv16,  g_Wv16);
    cudaGetSymbolAddress((void**)&Wo16,  g_Wo16);
    cudaGetSymbolAddress((void**)&Q16,   g_Q16);
    cudaGetSymbolAddress((void**)&K16,   g_K16);
    cudaGetSymbolAddress((void**)&Vt16,  g_Vt16);

    cudaFuncSetAttribute(hmma_gemm_kernel,
                         cudaFuncAttributeMaxDynamicSharedMemorySize,
                         GEMM_SMEM_BYTES);
    cudaFuncSetAttribute(attn_hmma_kernel,
                         cudaFuncAttributeMaxDynamicSharedMemorySize,
                         ATT_SMEM_BYTES);

    const int nX4 = MROWS * EMBED / 4;

    // 1) conversions + fused QK weight/bias
    f32_to_f16_kernel<<<(nX4 + 255) / 256, 256>>>(X, X16, nX4);
    transpose_f16_kernel<<<dim3(QKCOLS / 32, EMBED / 32), 256>>>(Wq, Wqk16, QKCOLS);
    transpose_f16_kernel<<<dim3(QKCOLS / 32, EMBED / 32), 256>>>(
        Wk, Wqk16 + (size_t)QKCOLS * EMBED, QKCOLS);
    transpose_f16_kernel<<<dim3(EMBED / 32, EMBED / 32), 256>>>(Wv, Wv16, EMBED);
    transpose_f16_kernel<<<dim3(EMBED / 32, EMBED / 32), 256>>>(Wo, Wo16, EMBED);
    cudaMemcpyAsync(bqk,          bq, QKCOLS * sizeof(float), cudaMemcpyDeviceToDevice);
    cudaMemcpyAsync(bqk + QKCOLS, bk, QKCOLS * sizeof(float), cudaMemcpyDeviceToDevice);

    // 2) projections: fused QK GEMM + V GEMM
    hmma_gemm_kernel<<<dim3(2 * QKCOLS / 128, MROWS / 128), 256, GEMM_SMEM_BYTES>>>(
        X16, Wqk16, bqk, QKp, 2 * QKCOLS);
    hmma_gemm_kernel<<<dim3(EMBED / 128, MROWS / 128), 256, GEMM_SMEM_BYTES>>>(
        X16, Wv16, bv, Vp, EMBED);

    // 3) attention prep
    prep_qk_kernel<<<dim3(MROWS * QKCOLS / 4 / 256, 2), 256>>>(QKp, Q16, K16);
    prep_vt_kernel<<<dim3(S_LEN / 32, EMBED / 32, BATCH), 256>>>(Vp, Vt16);

    // 4) attention
    attn_hmma_kernel<<<dim3(S_LEN / 128, BH), 256, ATT_SMEM_BYTES>>>(
        Q16, K16, Vt16, AOp);

    // 5) output projection
    f32_to_f16_kernel<<<(nX4 + 255) / 256, 256>>>(AOp, AO16, nX4);
    hmma_gemm_kernel<<<dim3(EMBED / 128, MROWS / 128), 256, GEMM_SMEM_BYTES>>>(
        AO16, Wo16, bo, out, EMBED);
}